// round 1
// baseline (speedup 1.0000x reference)
#include <cuda_runtime.h>
#include <cuda_bf16.h>

// Problem constants (B=2, T=2048, C=1024, H=16, D=64)
#define BATCH   2
#define SEQ     2048
#define EMBD    1024
#define NHEAD   16
#define HDIM    64
#define ROWS    (BATCH * SEQ)          // 4096
#define QKVC    (3 * EMBD)             // 3072

// Static device scratch (allocation-free rule)
__device__ float g_qkv[ROWS * QKVC];   // [4096, 3072]  q|k|v
__device__ float g_y  [ROWS * EMBD];   // [4096, 1024]  attention output

// ---------------------------------------------------------------------------
// Tiled SGEMM + bias:  C[M,N] = A[M,K] @ B[K,N] + bias[N]
// BM=BN=128, BK=8, TM=TN=8, 256 threads. All dims divisible, no bounds checks.
// ---------------------------------------------------------------------------
template <int BM, int BN, int BK, int TM, int TN>
__global__ __launch_bounds__(256)
void sgemm_bias_kernel(const float* __restrict__ A,
                       const float* __restrict__ B,
                       const float* __restrict__ bias,
                       float* __restrict__ C,
                       int M, int N, int K)
{
    __shared__ float As[BK][BM];
    __shared__ float Bs[BK][BN];

    const int tid = threadIdx.x;
    const int threadCol = tid % (BN / TN);   // 0..15
    const int threadRow = tid / (BN / TN);   // 0..15

    const int cRow = blockIdx.y;
    const int cCol = blockIdx.x;

    A += (size_t)cRow * BM * K;
    B += (size_t)cCol * BN;
    C += (size_t)cRow * BM * N + (size_t)cCol * BN;

    // A tile: 128 rows x 8 cols -> 256 float4 loads (1 per thread)
    const int innerRowA = tid / (BK / 4);    // 0..127
    const int innerColA = tid % (BK / 4);    // 0..1
    // B tile: 8 rows x 128 cols -> 256 float4 loads (1 per thread)
    const int innerRowB = tid / (BN / 4);    // 0..7
    const int innerColB = tid % (BN / 4);    // 0..31

    float acc[TM][TN] = {};
    float regM[TM];
    float regN[TN];

    for (int k0 = 0; k0 < K; k0 += BK) {
        float4 a4 = *reinterpret_cast<const float4*>(A + innerRowA * K + innerColA * 4);
        As[innerColA * 4 + 0][innerRowA] = a4.x;
        As[innerColA * 4 + 1][innerRowA] = a4.y;
        As[innerColA * 4 + 2][innerRowA] = a4.z;
        As[innerColA * 4 + 3][innerRowA] = a4.w;

        *reinterpret_cast<float4*>(&Bs[innerRowB][innerColB * 4]) =
            *reinterpret_cast<const float4*>(B + innerRowB * N + innerColB * 4);

        __syncthreads();

        A += BK;
        B += (size_t)BK * N;

        #pragma unroll
        for (int k = 0; k < BK; k++) {
            #pragma unroll
            for (int i = 0; i < TM; i++) regM[i] = As[k][threadRow * TM + i];
            #pragma unroll
            for (int j = 0; j < TN; j++) regN[j] = Bs[k][threadCol * TN + j];
            #pragma unroll
            for (int i = 0; i < TM; i++)
                #pragma unroll
                for (int j = 0; j < TN; j++)
                    acc[i][j] += regM[i] * regN[j];
        }
        __syncthreads();
    }

    #pragma unroll
    for (int i = 0; i < TM; i++) {
        const int row = threadRow * TM + i;
        #pragma unroll
        for (int j = 0; j < TN; j += 4) {
            const int col = threadCol * TN + j;
            float4 o;
            o.x = acc[i][j + 0] + bias[cCol * BN + col + 0];
            o.y = acc[i][j + 1] + bias[cCol * BN + col + 1];
            o.z = acc[i][j + 2] + bias[cCol * BN + col + 2];
            o.w = acc[i][j + 3] + bias[cCol * BN + col + 3];
            *reinterpret_cast<float4*>(&C[(size_t)row * N + col]) = o;
        }
    }
}

// ---------------------------------------------------------------------------
// Flash attention (fp32, online softmax), causal.
// Grid: (SEQ/TQ, BATCH*NHEAD). 128 threads; each thread owns one query row:
// q[64] and acc[64] live in registers; K/V tiles (32 keys x 64) in smem,
// read as broadcast LDS.128 (conflict-free).
// ---------------------------------------------------------------------------
#define TQ 128
#define TK 32

__global__ __launch_bounds__(TQ)
void flash_attn_kernel(const float* __restrict__ qkv, float* __restrict__ y)
{
    const int b = blockIdx.y >> 4;          // /16
    const int h = blockIdx.y & 15;
    const int tid = threadIdx.x;
    const int tq = blockIdx.x * TQ + tid;   // global query index within sequence

    const float* base = qkv + (size_t)b * SEQ * QKVC;

    // load q row into registers
    float q[HDIM];
    {
        const float* qrow = base + (size_t)tq * QKVC + h * HDIM;
        #pragma unroll
        for (int d = 0; d < HDIM; d += 4) {
            float4 v4 = *reinterpret_cast<const float4*>(qrow + d);
            q[d + 0] = v4.x; q[d + 1] = v4.y; q[d + 2] = v4.z; q[d + 3] = v4.w;
        }
    }

    float acc[HDIM];
    #pragma unroll
    for (int d = 0; d < HDIM; d++) acc[d] = 0.f;
    float m = -1e30f;
    float l = 0.f;

    __shared__ float Ks[TK][HDIM];
    __shared__ float Vs[TK][HDIM];

    const int ntiles = (blockIdx.x * TQ + TQ) / TK;   // enough tiles to cover max query in block

    for (int kt = 0; kt < ntiles; kt++) {
        // cooperative tile load: TK*HDIM/4 = 512 float4, 128 threads -> 4 each
        #pragma unroll
        for (int i = 0; i < (TK * HDIM) / (4 * TQ); i++) {
            const int lin = i * TQ + tid;          // 0..511
            const int key = lin >> 4;              // /16
            const int d4  = lin & 15;
            const float* gp = base + (size_t)(kt * TK + key) * QKVC + h * HDIM + d4 * 4;
            *reinterpret_cast<float4*>(&Ks[key][d4 * 4]) =
                *reinterpret_cast<const float4*>(gp + EMBD);        // K block
            *reinterpret_cast<float4*>(&Vs[key][d4 * 4]) =
                *reinterpret_cast<const float4*>(gp + 2 * EMBD);    // V block
        }
        __syncthreads();

        // scores for this thread's query vs TK keys
        float s[TK];
        #pragma unroll
        for (int j = 0; j < TK; j++) {
            float dot = 0.f;
            #pragma unroll
            for (int d = 0; d < HDIM; d += 4) {
                float4 k4 = *reinterpret_cast<const float4*>(&Ks[j][d]);
                dot += q[d + 0] * k4.x + q[d + 1] * k4.y
                     + q[d + 2] * k4.z + q[d + 3] * k4.w;
            }
            const int gk = kt * TK + j;
            s[j] = (gk <= tq) ? dot * 0.125f : -1e30f;   // scale = 1/sqrt(64)
        }

        // online softmax update
        float mt = m;
        #pragma unroll
        for (int j = 0; j < TK; j++) mt = fmaxf(mt, s[j]);
        const float corr = __expf(m - mt);
        float psum = 0.f;
        #pragma unroll
        for (int j = 0; j < TK; j++) {
            s[j] = __expf(s[j] - mt);
            psum += s[j];
        }
        l = l * corr + psum;
        m = mt;

        #pragma unroll
        for (int d = 0; d < HDIM; d++) acc[d] *= corr;

        #pragma unroll
        for (int j = 0; j < TK; j++) {
            const float p = s[j];
            #pragma unroll
            for (int d = 0; d < HDIM; d += 4) {
                float4 v4 = *reinterpret_cast<const float4*>(&Vs[j][d]);
                acc[d + 0] += p * v4.x;
                acc[d + 1] += p * v4.y;
                acc[d + 2] += p * v4.z;
                acc[d + 3] += p * v4.w;
            }
        }
        __syncthreads();
    }

    // epilogue: normalize and write y[b, tq, h*64 + d]
    const float inv = 1.f / l;
    float* yp = y + (size_t)(b * SEQ + tq) * EMBD + h * HDIM;
    #pragma unroll
    for (int d = 0; d < HDIM; d += 4) {
        float4 o;
        o.x = acc[d + 0] * inv;
        o.y = acc[d + 1] * inv;
        o.z = acc[d + 2] * inv;
        o.w = acc[d + 3] * inv;
        *reinterpret_cast<float4*>(yp + d) = o;
    }
}

// ---------------------------------------------------------------------------
// Launch: QKV GEMM -> flash attention -> proj GEMM (same stream, ordered)
// ---------------------------------------------------------------------------
extern "C" void kernel_launch(void* const* d_in, const int* in_sizes, int n_in,
                              void* d_out, int out_size)
{
    const float* x      = (const float*)d_in[0];
    const float* w_attn = (const float*)d_in[1];
    const float* b_attn = (const float*)d_in[2];
    const float* w_proj = (const float*)d_in[3];
    const float* b_proj = (const float*)d_in[4];
    float* out = (float*)d_out;

    float* qkv = nullptr;
    float* y   = nullptr;
    cudaGetSymbolAddress((void**)&qkv, g_qkv);
    cudaGetSymbolAddress((void**)&y,   g_y);

    // QKV: [4096,1024] @ [1024,3072] + b_attn
    sgemm_bias_kernel<128, 128, 8, 8, 8>
        <<<dim3(QKVC / 128, ROWS / 128), 256>>>(x, w_attn, b_attn, qkv,
                                                ROWS, QKVC, EMBD);

    // Attention: per (batch*head, query tile)
    flash_attn_kernel<<<dim3(SEQ / TQ, BATCH * NHEAD), TQ>>>(qkv, y);

    // Proj: [4096,1024] @ [1024,1024] + b_proj
    sgemm_bias_kernel<128, 128, 8, 8, 8>
        <<<dim3(EMBD / 128, ROWS / 128), 256>>>(y, w_proj, b_proj, out,
                                                ROWS, EMBD, EMBD);
}

// round 2
// speedup vs baseline: 1.3261x; 1.3261x over previous
#include <cuda_runtime.h>
#include <cuda_bf16.h>
#include <cstdint>

// Problem constants (B=2, T=2048, C=1024, H=16, D=64)
#define BATCH   2
#define SEQ     2048
#define EMBD    1024
#define NHEAD   16
#define HDIM    64
#define ROWS    (BATCH * SEQ)          // 4096
#define QKVC    (3 * EMBD)             // 3072

// Static device scratch (allocation-free rule)
__device__ float g_qkv[ROWS * QKVC];   // [4096, 3072]  q|k|v
__device__ float g_y  [ROWS * EMBD];   // [4096, 1024]  attention output

// ---------------------------------------------------------------------------
// tf32 helpers
// ---------------------------------------------------------------------------
__device__ __forceinline__ float tf32r(float x) {
    // round-to-nearest tf32 (unbiased); result is a valid fp32 bit pattern
    uint32_t y;
    asm("cvt.rna.tf32.f32 %0, %1;" : "=r"(y) : "f"(x));
    return __uint_as_float(y);
}

__device__ __forceinline__ void mma_tf32(float* c, const uint32_t* a, const uint32_t* b) {
    asm volatile(
        "mma.sync.aligned.m16n8k8.row.col.f32.tf32.tf32.f32 "
        "{%0,%1,%2,%3}, {%4,%5,%6,%7}, {%8,%9}, {%0,%1,%2,%3};\n"
        : "+f"(c[0]), "+f"(c[1]), "+f"(c[2]), "+f"(c[3])
        : "r"(a[0]), "r"(a[1]), "r"(a[2]), "r"(a[3]),
          "r"(b[0]), "r"(b[1]));
}

// ---------------------------------------------------------------------------
// tf32 tensor-core GEMM + bias:  C[M,N] = A[M,K] @ B[K,N] + bias[N]
// CTA tile 128x128x16, 8 warps (4x2), warp tile 32x64, mma m16n8k8.
// Smem stride BM+8=136 -> bank = (8k + m) % 32, all 32 distinct:
// conflict-free STS and fragment LDS. Double-buffered, register prefetch.
// ---------------------------------------------------------------------------
#define GBM 128
#define GBN 128
#define GBK 16
#define GSA (GBM + 8)   // 136
#define GSB (GBN + 8)   // 136

__global__ __launch_bounds__(256)
void gemm_tf32_bias(const float* __restrict__ A,
                    const float* __restrict__ B,
                    const float* __restrict__ bias,
                    float* __restrict__ C,
                    int M, int N, int K)
{
    __shared__ float As[2][GBK][GSA];
    __shared__ float Bs[2][GBK][GSB];

    const int tid   = threadIdx.x;
    const int lane  = tid & 31;
    const int warp  = tid >> 5;
    const int warpM = warp & 3;      // 0..3 (4 * 32 = 128 along M)
    const int warpN = warp >> 2;     // 0..1 (2 * 64 = 128 along N)
    const int tg    = lane & 3;      // threadID_in_group
    const int gp    = lane >> 2;     // groupID

    const int blockM = blockIdx.y;
    const int blockN = blockIdx.x;

    const float* Ab = A + (size_t)blockM * GBM * K;
    const float* Bb = B + (size_t)blockN * GBN;

    // A tile loads: 128(m) x 16(k); thread -> row tid&127, k-quad tid>>7
    const int aRow = tid & 127;
    const int aK   = (tid >> 7) * 4;     // 0 or 4 (plus +8 on second iter)
    // B tile loads: 16(k) x 128(n); thread -> row tid>>5, col-quad tid&31
    const int bRow = tid >> 5;           // 0..7 (plus +8 on second pass)
    const int bCol = (tid & 31) * 4;

    float acc[2][8][4];
    #pragma unroll
    for (int mt = 0; mt < 2; mt++)
        #pragma unroll
        for (int nt = 0; nt < 8; nt++)
            #pragma unroll
            for (int i = 0; i < 4; i++) acc[mt][nt][i] = 0.f;

    const int NT = K / GBK;

    // --- preload tile 0 into buffer 0 ---
    {
        #pragma unroll
        for (int i = 0; i < 2; i++) {
            const int k = aK + i * 8;
            float4 v = *reinterpret_cast<const float4*>(Ab + (size_t)aRow * K + k);
            As[0][k + 0][aRow] = tf32r(v.x);
            As[0][k + 1][aRow] = tf32r(v.y);
            As[0][k + 2][aRow] = tf32r(v.z);
            As[0][k + 3][aRow] = tf32r(v.w);
        }
        #pragma unroll
        for (int p = 0; p < 2; p++) {
            const int k = bRow + p * 8;
            float4 v = *reinterpret_cast<const float4*>(Bb + (size_t)k * N + bCol);
            float4 w = make_float4(tf32r(v.x), tf32r(v.y), tf32r(v.z), tf32r(v.w));
            *reinterpret_cast<float4*>(&Bs[0][k][bCol]) = w;
        }
    }
    __syncthreads();

    for (int kt = 0; kt < NT; kt++) {
        const int buf = kt & 1;

        // register prefetch of next tile
        float4 pa[2], pb[2];
        if (kt + 1 < NT) {
            const int kBase = (kt + 1) * GBK;
            #pragma unroll
            for (int i = 0; i < 2; i++) {
                const int k = aK + i * 8;
                pa[i] = *reinterpret_cast<const float4*>(Ab + (size_t)aRow * K + kBase + k);
            }
            #pragma unroll
            for (int p = 0; p < 2; p++) {
                const int k = bRow + p * 8;
                pb[p] = *reinterpret_cast<const float4*>(Bb + (size_t)(kBase + k) * N + bCol);
            }
        }

        // compute on current buffer: 2 k-steps of 8
        #pragma unroll
        for (int ks = 0; ks < 2; ks++) {
            const int k0 = ks * 8;
            uint32_t afr[2][4];
            uint32_t bfr[8][2];
            #pragma unroll
            for (int mt = 0; mt < 2; mt++) {
                const int m0 = warpM * 32 + mt * 16 + gp;
                afr[mt][0] = __float_as_uint(As[buf][k0 + tg    ][m0]);
                afr[mt][1] = __float_as_uint(As[buf][k0 + tg    ][m0 + 8]);
                afr[mt][2] = __float_as_uint(As[buf][k0 + tg + 4][m0]);
                afr[mt][3] = __float_as_uint(As[buf][k0 + tg + 4][m0 + 8]);
            }
            #pragma unroll
            for (int nt = 0; nt < 8; nt++) {
                const int n0 = warpN * 64 + nt * 8 + gp;
                bfr[nt][0] = __float_as_uint(Bs[buf][k0 + tg    ][n0]);
                bfr[nt][1] = __float_as_uint(Bs[buf][k0 + tg + 4][n0]);
            }
            #pragma unroll
            for (int mt = 0; mt < 2; mt++)
                #pragma unroll
                for (int nt = 0; nt < 8; nt++)
                    mma_tf32(acc[mt][nt], afr[mt], bfr[nt]);
        }

        // store prefetched tile into other buffer
        if (kt + 1 < NT) {
            const int nbuf = buf ^ 1;
            #pragma unroll
            for (int i = 0; i < 2; i++) {
                const int k = aK + i * 8;
                As[nbuf][k + 0][aRow] = tf32r(pa[i].x);
                As[nbuf][k + 1][aRow] = tf32r(pa[i].y);
                As[nbuf][k + 2][aRow] = tf32r(pa[i].z);
                As[nbuf][k + 3][aRow] = tf32r(pa[i].w);
            }
            #pragma unroll
            for (int p = 0; p < 2; p++) {
                const int k = bRow + p * 8;
                float4 w = make_float4(tf32r(pb[p].x), tf32r(pb[p].y),
                                       tf32r(pb[p].z), tf32r(pb[p].w));
                *reinterpret_cast<float4*>(&Bs[nbuf][k][bCol]) = w;
            }
        }
        __syncthreads();
    }

    // epilogue: bias add + store (float2 per fragment half)
    #pragma unroll
    for (int mt = 0; mt < 2; mt++) {
        const int r0 = blockM * GBM + warpM * 32 + mt * 16 + gp;
        #pragma unroll
        for (int nt = 0; nt < 8; nt++) {
            const int c = blockN * GBN + warpN * 64 + nt * 8 + tg * 2;
            const float b0 = bias[c];
            const float b1 = bias[c + 1];
            float2 v0 = make_float2(acc[mt][nt][0] + b0, acc[mt][nt][1] + b1);
            float2 v1 = make_float2(acc[mt][nt][2] + b0, acc[mt][nt][3] + b1);
            *reinterpret_cast<float2*>(&C[(size_t)r0 * N + c])       = v0;
            *reinterpret_cast<float2*>(&C[(size_t)(r0 + 8) * N + c]) = v1;
        }
    }
}

// ---------------------------------------------------------------------------
// Flash attention (fp32, online softmax), causal.
// Grid: (SEQ/TQ, BATCH*NHEAD). 128 threads; each thread owns one query row.
// Longest-work blocks are scheduled first (reversed qtile) for load balance.
// ---------------------------------------------------------------------------
#define TQ 128
#define TK 32

__global__ __launch_bounds__(TQ)
void flash_attn_kernel(const float* __restrict__ qkv, float* __restrict__ y)
{
    const int b = blockIdx.y >> 4;          // /16
    const int h = blockIdx.y & 15;
    const int tid = threadIdx.x;
    const int qtile = gridDim.x - 1 - blockIdx.x;   // longest-first scheduling
    const int tq = qtile * TQ + tid;        // global query index within sequence

    const float* base = qkv + (size_t)b * SEQ * QKVC;

    float q[HDIM];
    {
        const float* qrow = base + (size_t)tq * QKVC + h * HDIM;
        #pragma unroll
        for (int d = 0; d < HDIM; d += 4) {
            float4 v4 = *reinterpret_cast<const float4*>(qrow + d);
            q[d + 0] = v4.x; q[d + 1] = v4.y; q[d + 2] = v4.z; q[d + 3] = v4.w;
        }
    }

    float acc[HDIM];
    #pragma unroll
    for (int d = 0; d < HDIM; d++) acc[d] = 0.f;
    float m = -1e30f;
    float l = 0.f;

    __shared__ float Ks[TK][HDIM];
    __shared__ float Vs[TK][HDIM];

    const int ntiles = (qtile * TQ + TQ) / TK;

    for (int kt = 0; kt < ntiles; kt++) {
        #pragma unroll
        for (int i = 0; i < (TK * HDIM) / (4 * TQ); i++) {
            const int lin = i * TQ + tid;          // 0..511
            const int key = lin >> 4;
            const int d4  = lin & 15;
            const float* gp = base + (size_t)(kt * TK + key) * QKVC + h * HDIM + d4 * 4;
            *reinterpret_cast<float4*>(&Ks[key][d4 * 4]) =
                *reinterpret_cast<const float4*>(gp + EMBD);
            *reinterpret_cast<float4*>(&Vs[key][d4 * 4]) =
                *reinterpret_cast<const float4*>(gp + 2 * EMBD);
        }
        __syncthreads();

        float s[TK];
        #pragma unroll
        for (int j = 0; j < TK; j++) {
            float dot = 0.f;
            #pragma unroll
            for (int d = 0; d < HDIM; d += 4) {
                float4 k4 = *reinterpret_cast<const float4*>(&Ks[j][d]);
                dot += q[d + 0] * k4.x + q[d + 1] * k4.y
                     + q[d + 2] * k4.z + q[d + 3] * k4.w;
            }
            const int gk = kt * TK + j;
            s[j] = (gk <= tq) ? dot * 0.125f : -1e30f;
        }

        float mt = m;
        #pragma unroll
        for (int j = 0; j < TK; j++) mt = fmaxf(mt, s[j]);
        const float corr = __expf(m - mt);
        float psum = 0.f;
        #pragma unroll
        for (int j = 0; j < TK; j++) {
            s[j] = __expf(s[j] - mt);
            psum += s[j];
        }
        l = l * corr + psum;
        m = mt;

        #pragma unroll
        for (int d = 0; d < HDIM; d++) acc[d] *= corr;

        #pragma unroll
        for (int j = 0; j < TK; j++) {
            const float p = s[j];
            #pragma unroll
            for (int d = 0; d < HDIM; d += 4) {
                float4 v4 = *reinterpret_cast<const float4*>(&Vs[j][d]);
                acc[d + 0] += p * v4.x;
                acc[d + 1] += p * v4.y;
                acc[d + 2] += p * v4.z;
                acc[d + 3] += p * v4.w;
            }
        }
        __syncthreads();
    }

    const float inv = 1.f / l;
    float* yp = y + (size_t)(b * SEQ + tq) * EMBD + h * HDIM;
    #pragma unroll
    for (int d = 0; d < HDIM; d += 4) {
        float4 o;
        o.x = acc[d + 0] * inv;
        o.y = acc[d + 1] * inv;
        o.z = acc[d + 2] * inv;
        o.w = acc[d + 3] * inv;
        *reinterpret_cast<float4*>(yp + d) = o;
    }
}

// ---------------------------------------------------------------------------
// Launch: QKV GEMM -> flash attention -> proj GEMM (same stream, ordered)
// ---------------------------------------------------------------------------
extern "C" void kernel_launch(void* const* d_in, const int* in_sizes, int n_in,
                              void* d_out, int out_size)
{
    const float* x      = (const float*)d_in[0];
    const float* w_attn = (const float*)d_in[1];
    const float* b_attn = (const float*)d_in[2];
    const float* w_proj = (const float*)d_in[3];
    const float* b_proj = (const float*)d_in[4];
    float* out = (float*)d_out;

    float* qkv = nullptr;
    float* y   = nullptr;
    cudaGetSymbolAddress((void**)&qkv, g_qkv);
    cudaGetSymbolAddress((void**)&y,   g_y);

    // QKV: [4096,1024] @ [1024,3072] + b_attn
    gemm_tf32_bias<<<dim3(QKVC / GBN, ROWS / GBM), 256>>>(x, w_attn, b_attn, qkv,
                                                          ROWS, QKVC, EMBD);

    // Attention: per (batch*head, query tile)
    flash_attn_kernel<<<dim3(SEQ / TQ, BATCH * NHEAD), TQ>>>(qkv, y);

    // Proj: [4096,1024] @ [1024,1024] + b_proj
    gemm_tf32_bias<<<dim3(EMBD / GBN, ROWS / GBM), 256>>>(y, w_proj, b_proj, out,
                                                          ROWS, EMBD, EMBD);
}

// round 3
// speedup vs baseline: 2.5719x; 1.9395x over previous
#include <cuda_runtime.h>
#include <cuda_bf16.h>
#include <cstdint>

// Problem constants (B=2, T=2048, C=1024, H=16, D=64)
#define BATCH   2
#define SEQ     2048
#define EMBD    1024
#define NHEAD   16
#define HDIM    64
#define ROWS    (BATCH * SEQ)          // 4096
#define QKVC    (3 * EMBD)             // 3072

// Static device scratch (allocation-free rule)
__device__ float g_qkv[ROWS * QKVC];   // [4096, 3072]  q|k|v
__device__ float g_y  [ROWS * EMBD];   // [4096, 1024]  attention output

// ---------------------------------------------------------------------------
// tf32 helpers
// ---------------------------------------------------------------------------
__device__ __forceinline__ float tf32r(float x) {
    uint32_t y;
    asm("cvt.rna.tf32.f32 %0, %1;" : "=r"(y) : "f"(x));
    return __uint_as_float(y);
}
__device__ __forceinline__ uint32_t tf32u(float x) {
    uint32_t y;
    asm("cvt.rna.tf32.f32 %0, %1;" : "=r"(y) : "f"(x));
    return y;
}

__device__ __forceinline__ void mma_tf32(float* c, const uint32_t* a, const uint32_t* b) {
    asm volatile(
        "mma.sync.aligned.m16n8k8.row.col.f32.tf32.tf32.f32 "
        "{%0,%1,%2,%3}, {%4,%5,%6,%7}, {%8,%9}, {%0,%1,%2,%3};\n"
        : "+f"(c[0]), "+f"(c[1]), "+f"(c[2]), "+f"(c[3])
        : "r"(a[0]), "r"(a[1]), "r"(a[2]), "r"(a[3]),
          "r"(b[0]), "r"(b[1]));
}

// ---------------------------------------------------------------------------
// tf32 tensor-core GEMM + bias:  C[M,N] = A[M,K] @ B[K,N] + bias[N]
// (unchanged from round 2)
// ---------------------------------------------------------------------------
#define GBM 128
#define GBN 128
#define GBK 16
#define GSA (GBM + 8)   // 136
#define GSB (GBN + 8)   // 136

__global__ __launch_bounds__(256)
void gemm_tf32_bias(const float* __restrict__ A,
                    const float* __restrict__ B,
                    const float* __restrict__ bias,
                    float* __restrict__ C,
                    int M, int N, int K)
{
    __shared__ float As[2][GBK][GSA];
    __shared__ float Bs[2][GBK][GSB];

    const int tid   = threadIdx.x;
    const int lane  = tid & 31;
    const int warp  = tid >> 5;
    const int warpM = warp & 3;
    const int warpN = warp >> 2;
    const int tg    = lane & 3;
    const int gp    = lane >> 2;

    const int blockM = blockIdx.y;
    const int blockN = blockIdx.x;

    const float* Ab = A + (size_t)blockM * GBM * K;
    const float* Bb = B + (size_t)blockN * GBN;

    const int aRow = tid & 127;
    const int aK   = (tid >> 7) * 4;
    const int bRow = tid >> 5;
    const int bCol = (tid & 31) * 4;

    float acc[2][8][4];
    #pragma unroll
    for (int mt = 0; mt < 2; mt++)
        #pragma unroll
        for (int nt = 0; nt < 8; nt++)
            #pragma unroll
            for (int i = 0; i < 4; i++) acc[mt][nt][i] = 0.f;

    const int NT = K / GBK;

    {
        #pragma unroll
        for (int i = 0; i < 2; i++) {
            const int k = aK + i * 8;
            float4 v = *reinterpret_cast<const float4*>(Ab + (size_t)aRow * K + k);
            As[0][k + 0][aRow] = tf32r(v.x);
            As[0][k + 1][aRow] = tf32r(v.y);
            As[0][k + 2][aRow] = tf32r(v.z);
            As[0][k + 3][aRow] = tf32r(v.w);
        }
        #pragma unroll
        for (int p = 0; p < 2; p++) {
            const int k = bRow + p * 8;
            float4 v = *reinterpret_cast<const float4*>(Bb + (size_t)k * N + bCol);
            float4 w = make_float4(tf32r(v.x), tf32r(v.y), tf32r(v.z), tf32r(v.w));
            *reinterpret_cast<float4*>(&Bs[0][k][bCol]) = w;
        }
    }
    __syncthreads();

    for (int kt = 0; kt < NT; kt++) {
        const int buf = kt & 1;

        float4 pa[2], pb[2];
        if (kt + 1 < NT) {
            const int kBase = (kt + 1) * GBK;
            #pragma unroll
            for (int i = 0; i < 2; i++) {
                const int k = aK + i * 8;
                pa[i] = *reinterpret_cast<const float4*>(Ab + (size_t)aRow * K + kBase + k);
            }
            #pragma unroll
            for (int p = 0; p < 2; p++) {
                const int k = bRow + p * 8;
                pb[p] = *reinterpret_cast<const float4*>(Bb + (size_t)(kBase + k) * N + bCol);
            }
        }

        #pragma unroll
        for (int ks = 0; ks < 2; ks++) {
            const int k0 = ks * 8;
            uint32_t afr[2][4];
            uint32_t bfr[8][2];
            #pragma unroll
            for (int mt = 0; mt < 2; mt++) {
                const int m0 = warpM * 32 + mt * 16 + gp;
                afr[mt][0] = __float_as_uint(As[buf][k0 + tg    ][m0]);
                afr[mt][1] = __float_as_uint(As[buf][k0 + tg    ][m0 + 8]);
                afr[mt][2] = __float_as_uint(As[buf][k0 + tg + 4][m0]);
                afr[mt][3] = __float_as_uint(As[buf][k0 + tg + 4][m0 + 8]);
            }
            #pragma unroll
            for (int nt = 0; nt < 8; nt++) {
                const int n0 = warpN * 64 + nt * 8 + gp;
                bfr[nt][0] = __float_as_uint(Bs[buf][k0 + tg    ][n0]);
                bfr[nt][1] = __float_as_uint(Bs[buf][k0 + tg + 4][n0]);
            }
            #pragma unroll
            for (int mt = 0; mt < 2; mt++)
                #pragma unroll
                for (int nt = 0; nt < 8; nt++)
                    mma_tf32(acc[mt][nt], afr[mt], bfr[nt]);
        }

        if (kt + 1 < NT) {
            const int nbuf = buf ^ 1;
            #pragma unroll
            for (int i = 0; i < 2; i++) {
                const int k = aK + i * 8;
                As[nbuf][k + 0][aRow] = tf32r(pa[i].x);
                As[nbuf][k + 1][aRow] = tf32r(pa[i].y);
                As[nbuf][k + 2][aRow] = tf32r(pa[i].z);
                As[nbuf][k + 3][aRow] = tf32r(pa[i].w);
            }
            #pragma unroll
            for (int p = 0; p < 2; p++) {
                const int k = bRow + p * 8;
                float4 w = make_float4(tf32r(pb[p].x), tf32r(pb[p].y),
                                       tf32r(pb[p].z), tf32r(pb[p].w));
                *reinterpret_cast<float4*>(&Bs[nbuf][k][bCol]) = w;
            }
        }
        __syncthreads();
    }

    #pragma unroll
    for (int mt = 0; mt < 2; mt++) {
        const int r0 = blockM * GBM + warpM * 32 + mt * 16 + gp;
        #pragma unroll
        for (int nt = 0; nt < 8; nt++) {
            const int c = blockN * GBN + warpN * 64 + nt * 8 + tg * 2;
            const float b0 = bias[c];
            const float b1 = bias[c + 1];
            float2 v0 = make_float2(acc[mt][nt][0] + b0, acc[mt][nt][1] + b1);
            float2 v1 = make_float2(acc[mt][nt][2] + b0, acc[mt][nt][3] + b1);
            *reinterpret_cast<float2*>(&C[(size_t)r0 * N + c])       = v0;
            *reinterpret_cast<float2*>(&C[(size_t)(r0 + 8) * N + c]) = v1;
        }
    }
}

// ---------------------------------------------------------------------------
// Tensor-core flash attention (tf32 mma, fp32 softmax), causal.
// Block: 128 threads = 4 warps; block tile = 64 queries x (K in 64-key tiles).
// Warp owns 16 query rows. Q fragments in registers, K tile in smem
// (stride 68: conflict-free STS+LDS), V read straight from gmem in
// B-fragment layout (natural [key][d] order), P converted C->A layout by shfl.
// ---------------------------------------------------------------------------
#define ATQ 64
#define ATK 64
#define KSP 68

__global__ __launch_bounds__(128)
void flash_attn_tc(const float* __restrict__ qkv, float* __restrict__ y)
{
    __shared__ float Ks[ATK][KSP];

    const int bh  = blockIdx.y;
    const int b   = bh >> 4;
    const int h   = bh & 15;
    const int qt  = gridDim.x - 1 - blockIdx.x;   // longest-first
    const int q0  = qt * ATQ;
    const int tid = threadIdx.x;
    const int lane = tid & 31;
    const int w    = tid >> 5;
    const int tg   = lane & 3;
    const int gp   = lane >> 2;

    const float* base = qkv + (size_t)b * SEQ * QKVC;
    const float* Qb = base + h * HDIM;
    const float* Kb = base + EMBD + h * HDIM;
    const float* Vb = base + 2 * EMBD + h * HDIM;

    const int qrow = q0 + w * 16 + gp;            // this thread's low query row

    // Q fragments for all 8 k-steps (row-major A, m16k8)
    uint32_t qfr[8][4];
    #pragma unroll
    for (int ks = 0; ks < 8; ks++) {
        const float* p0 = Qb + (size_t)qrow * QKVC + ks * 8;
        const float* p1 = Qb + (size_t)(qrow + 8) * QKVC + ks * 8;
        qfr[ks][0] = tf32u(p0[tg]);
        qfr[ks][1] = tf32u(p1[tg]);
        qfr[ks][2] = tf32u(p0[tg + 4]);
        qfr[ks][3] = tf32u(p1[tg + 4]);
    }

    float oacc[8][4];
    #pragma unroll
    for (int dt = 0; dt < 8; dt++)
        #pragma unroll
        for (int i = 0; i < 4; i++) oacc[dt][i] = 0.f;

    float m_lo = -1e30f, m_hi = -1e30f;
    float l_lo = 0.f,    l_hi = 0.f;

    const int ntiles = qt + 1;
    for (int kt = 0; kt < ntiles; kt++) {
        // ---- stage K tile (64 keys x 64 dims), tf32-rounded ----
        #pragma unroll
        for (int i = 0; i < 8; i++) {
            const int lin = i * 128 + tid;
            const int key = lin >> 4;
            const int dq  = (lin & 15) * 4;
            float4 v = *reinterpret_cast<const float4*>(
                Kb + (size_t)(kt * ATK + key) * QKVC + dq);
            *reinterpret_cast<float4*>(&Ks[key][dq]) =
                make_float4(tf32r(v.x), tf32r(v.y), tf32r(v.z), tf32r(v.w));
        }
        __syncthreads();

        // ---- S = Q K^T  (8 n-tiles x 8 k-steps of m16n8k8) ----
        float sacc[8][4];
        #pragma unroll
        for (int nt = 0; nt < 8; nt++) {
            sacc[nt][0] = sacc[nt][1] = sacc[nt][2] = sacc[nt][3] = 0.f;
            #pragma unroll
            for (int ks = 0; ks < 8; ks++) {
                uint32_t bfr[2];
                bfr[0] = __float_as_uint(Ks[nt * 8 + gp][ks * 8 + tg]);
                bfr[1] = __float_as_uint(Ks[nt * 8 + gp][ks * 8 + tg + 4]);
                mma_tf32(sacc[nt], qfr[ks], bfr);
            }
        }

        // ---- scale + causal mask + online softmax ----
        const bool diag = (kt == qt);
        float tmax_lo = -1e30f, tmax_hi = -1e30f;
        #pragma unroll
        for (int nt = 0; nt < 8; nt++) {
            const int c0col = kt * ATK + nt * 8 + 2 * tg;
            float s0 = sacc[nt][0] * 0.125f;
            float s1 = sacc[nt][1] * 0.125f;
            float s2 = sacc[nt][2] * 0.125f;
            float s3 = sacc[nt][3] * 0.125f;
            if (diag) {
                if (c0col     > qrow)     s0 = -1e30f;
                if (c0col + 1 > qrow)     s1 = -1e30f;
                if (c0col     > qrow + 8) s2 = -1e30f;
                if (c0col + 1 > qrow + 8) s3 = -1e30f;
            }
            sacc[nt][0] = s0; sacc[nt][1] = s1;
            sacc[nt][2] = s2; sacc[nt][3] = s3;
            tmax_lo = fmaxf(tmax_lo, fmaxf(s0, s1));
            tmax_hi = fmaxf(tmax_hi, fmaxf(s2, s3));
        }
        tmax_lo = fmaxf(tmax_lo, __shfl_xor_sync(0xffffffffu, tmax_lo, 1));
        tmax_lo = fmaxf(tmax_lo, __shfl_xor_sync(0xffffffffu, tmax_lo, 2));
        tmax_hi = fmaxf(tmax_hi, __shfl_xor_sync(0xffffffffu, tmax_hi, 1));
        tmax_hi = fmaxf(tmax_hi, __shfl_xor_sync(0xffffffffu, tmax_hi, 2));

        const float mn_lo = fmaxf(m_lo, tmax_lo);
        const float mn_hi = fmaxf(m_hi, tmax_hi);
        const float corr_lo = __expf(m_lo - mn_lo);
        const float corr_hi = __expf(m_hi - mn_hi);
        m_lo = mn_lo; m_hi = mn_hi;

        float ps_lo = 0.f, ps_hi = 0.f;
        #pragma unroll
        for (int nt = 0; nt < 8; nt++) {
            float p0 = __expf(sacc[nt][0] - m_lo);
            float p1 = __expf(sacc[nt][1] - m_lo);
            float p2 = __expf(sacc[nt][2] - m_hi);
            float p3 = __expf(sacc[nt][3] - m_hi);
            sacc[nt][0] = p0; sacc[nt][1] = p1;
            sacc[nt][2] = p2; sacc[nt][3] = p3;
            ps_lo += p0 + p1;
            ps_hi += p2 + p3;
        }
        ps_lo += __shfl_xor_sync(0xffffffffu, ps_lo, 1);
        ps_lo += __shfl_xor_sync(0xffffffffu, ps_lo, 2);
        ps_hi += __shfl_xor_sync(0xffffffffu, ps_hi, 1);
        ps_hi += __shfl_xor_sync(0xffffffffu, ps_hi, 2);
        l_lo = l_lo * corr_lo + ps_lo;
        l_hi = l_hi * corr_hi + ps_hi;

        #pragma unroll
        for (int dt = 0; dt < 8; dt++) {
            oacc[dt][0] *= corr_lo;
            oacc[dt][1] *= corr_lo;
            oacc[dt][2] *= corr_hi;
            oacc[dt][3] *= corr_hi;
        }

        // ---- O += P V   (P: C-layout -> A-layout via shfl; V from gmem) ----
        #pragma unroll
        for (int kk = 0; kk < 8; kk++) {
            const float c0 = sacc[kk][0], c1 = sacc[kk][1];
            const float c2 = sacc[kk][2], c3 = sacc[kk][3];
            const int s1l = (lane & 28) + (tg >> 1);
            const int s2l = s1l + 2;
            float v00 = __shfl_sync(0xffffffffu, c0, s1l);
            float v01 = __shfl_sync(0xffffffffu, c1, s1l);
            float v20 = __shfl_sync(0xffffffffu, c2, s1l);
            float v21 = __shfl_sync(0xffffffffu, c3, s1l);
            float w00 = __shfl_sync(0xffffffffu, c0, s2l);
            float w01 = __shfl_sync(0xffffffffu, c1, s2l);
            float w20 = __shfl_sync(0xffffffffu, c2, s2l);
            float w21 = __shfl_sync(0xffffffffu, c3, s2l);
            const bool odd = (tg & 1);
            uint32_t pa[4];
            pa[0] = tf32u(odd ? v01 : v00);
            pa[1] = tf32u(odd ? v21 : v20);
            pa[2] = tf32u(odd ? w01 : w00);
            pa[3] = tf32u(odd ? w21 : w20);

            const float* vr0 = Vb + (size_t)(kt * ATK + kk * 8 + tg)     * QKVC;
            const float* vr1 = Vb + (size_t)(kt * ATK + kk * 8 + tg + 4) * QKVC;
            #pragma unroll
            for (int dt = 0; dt < 8; dt++) {
                uint32_t bv[2];
                bv[0] = tf32u(vr0[dt * 8 + gp]);
                bv[1] = tf32u(vr1[dt * 8 + gp]);
                mma_tf32(oacc[dt], pa, bv);
            }
        }
        __syncthreads();
    }

    // ---- epilogue: normalize and store ----
    const float inv_lo = 1.f / l_lo;
    const float inv_hi = 1.f / l_hi;
    float* y0 = y + (size_t)(b * SEQ + qrow)     * EMBD + h * HDIM;
    float* y1 = y + (size_t)(b * SEQ + qrow + 8) * EMBD + h * HDIM;
    #pragma unroll
    for (int dt = 0; dt < 8; dt++) {
        *reinterpret_cast<float2*>(y0 + dt * 8 + 2 * tg) =
            make_float2(oacc[dt][0] * inv_lo, oacc[dt][1] * inv_lo);
        *reinterpret_cast<float2*>(y1 + dt * 8 + 2 * tg) =
            make_float2(oacc[dt][2] * inv_hi, oacc[dt][3] * inv_hi);
    }
}

// ---------------------------------------------------------------------------
// Launch: QKV GEMM -> flash attention -> proj GEMM (same stream, ordered)
// ---------------------------------------------------------------------------
extern "C" void kernel_launch(void* const* d_in, const int* in_sizes, int n_in,
                              void* d_out, int out_size)
{
    const float* x      = (const float*)d_in[0];
    const float* w_attn = (const float*)d_in[1];
    const float* b_attn = (const float*)d_in[2];
    const float* w_proj = (const float*)d_in[3];
    const float* b_proj = (const float*)d_in[4];
    float* out = (float*)d_out;

    float* qkv = nullptr;
    float* y   = nullptr;
    cudaGetSymbolAddress((void**)&qkv, g_qkv);
    cudaGetSymbolAddress((void**)&y,   g_y);

    // QKV: [4096,1024] @ [1024,3072] + b_attn
    gemm_tf32_bias<<<dim3(QKVC / GBN, ROWS / GBM), 256>>>(x, w_attn, b_attn, qkv,
                                                          ROWS, QKVC, EMBD);

    // Attention
    flash_attn_tc<<<dim3(SEQ / ATQ, BATCH * NHEAD), 128>>>(qkv, y);

    // Proj: [4096,1024] @ [1024,1024] + b_proj
    gemm_tf32_bias<<<dim3(EMBD / GBN, ROWS / GBM), 256>>>(y, w_proj, b_proj, out,
                                                          ROWS, EMBD, EMBD);
}

// round 4
// speedup vs baseline: 4.5095x; 1.7534x over previous
#include <cuda_runtime.h>
#include <cuda_fp16.h>
#include <cstdint>

// Problem constants (B=2, T=2048, C=1024, H=16, D=64)
#define BATCH   2
#define SEQ     2048
#define EMBD    1024
#define NHEAD   16
#define HDIM    64
#define ROWS    (BATCH * SEQ)          // 4096
#define QKVC    (3 * EMBD)             // 3072

// Static device scratch (allocation-free rule)
__device__ __half g_xh  [ROWS * EMBD];   // x in fp16
__device__ __half g_wah [EMBD * QKVC];   // w_attn in fp16
__device__ __half g_wph [EMBD * EMBD];   // w_proj in fp16
__device__ __half g_qkvh[ROWS * QKVC];   // qkv (fp16)
__device__ __half g_yh  [ROWS * EMBD];   // attention output (fp16)

// ---------------------------------------------------------------------------
// helpers
// ---------------------------------------------------------------------------
__device__ __forceinline__ void mma_f16(float* c, const uint32_t* a, const uint32_t* b) {
    asm volatile(
        "mma.sync.aligned.m16n8k16.row.col.f32.f16.f16.f32 "
        "{%0,%1,%2,%3}, {%4,%5,%6,%7}, {%8,%9}, {%0,%1,%2,%3};\n"
        : "+f"(c[0]), "+f"(c[1]), "+f"(c[2]), "+f"(c[3])
        : "r"(a[0]), "r"(a[1]), "r"(a[2]), "r"(a[3]),
          "r"(b[0]), "r"(b[1]));
}

__device__ __forceinline__ void ldsm_x4(uint32_t* r, uint32_t saddr) {
    asm volatile("ldmatrix.sync.aligned.m8n8.x4.shared.b16 {%0,%1,%2,%3}, [%4];"
        : "=r"(r[0]), "=r"(r[1]), "=r"(r[2]), "=r"(r[3]) : "r"(saddr));
}
__device__ __forceinline__ void ldsm_x4_t(uint32_t* r, uint32_t saddr) {
    asm volatile("ldmatrix.sync.aligned.m8n8.x4.trans.shared.b16 {%0,%1,%2,%3}, [%4];"
        : "=r"(r[0]), "=r"(r[1]), "=r"(r[2]), "=r"(r[3]) : "r"(saddr));
}

__device__ __forceinline__ void cp16(const void* smem_dst, const void* gmem_src) {
    uint32_t d = (uint32_t)__cvta_generic_to_shared(smem_dst);
    asm volatile("cp.async.cg.shared.global [%0], [%1], 16;\n" :: "r"(d), "l"(gmem_src));
}
#define CP_COMMIT() asm volatile("cp.async.commit_group;\n" ::: "memory")
#define CP_WAIT1()  asm volatile("cp.async.wait_group 1;\n" ::: "memory")
#define CP_WAIT0()  asm volatile("cp.async.wait_group 0;\n" ::: "memory")

__device__ __forceinline__ uint32_t h2u(__half2 h) { return *reinterpret_cast<uint32_t*>(&h); }

// ---------------------------------------------------------------------------
// fp32 -> fp16 conversion (one-shot preprocessing)
// ---------------------------------------------------------------------------
__global__ void cvt_f2h(const float4* __restrict__ src, uint2* __restrict__ dst, int n4)
{
    int i = blockIdx.x * blockDim.x + threadIdx.x;
    if (i < n4) {
        float4 v = src[i];
        __half2 a = __floats2half2_rn(v.x, v.y);
        __half2 b = __floats2half2_rn(v.z, v.w);
        uint2 o;
        o.x = h2u(a);
        o.y = h2u(b);
        dst[i] = o;
    }
}

// ---------------------------------------------------------------------------
// fp16 tensor-core GEMM + bias: C[M,N] = A[M,K] @ B[K,N] + bias[N]
// CTA 128x128x32, 8 warps (4Mx2N), warp tile 32x64, mma m16n8k16.
// cp.async double-buffered staging; ldmatrix (A) / ldmatrix.trans (B).
// A rows padded to 40 halfs, B rows to 136 halfs -> conflict-free LDSM.
// HALF_OUT selects half (intermediate) or float (final) output.
// ---------------------------------------------------------------------------
#define HBM 128
#define HBN 128
#define HBK 32
#define ASP 40    // A row stride in halfs (32 + 8 pad): (5m+c)%8 distinct
#define BSP 136   // B row stride in halfs (128 + 8 pad): (k+c)%8 distinct

template<bool HALF_OUT>
__global__ __launch_bounds__(256)
void gemm_f16_bias(const __half* __restrict__ A,
                   const __half* __restrict__ B,
                   const float* __restrict__ bias,
                   void* __restrict__ Cv,
                   int M, int N, int K)
{
    __shared__ __align__(16) __half As[2][HBM][ASP];
    __shared__ __align__(16) __half Bs[2][HBK][BSP];

    const int tid  = threadIdx.x;
    const int lane = tid & 31;
    const int warp = tid >> 5;
    const int warpM = warp & 3;
    const int warpN = warp >> 2;
    const int tg = lane & 3;
    const int gp = lane >> 2;

    const int bm = blockIdx.y;
    const int bn = blockIdx.x;

    // staging assignments
    const int aRow = tid & 127;
    const int aCh  = tid >> 7;            // 0..1 -> chunks {aCh, aCh+2}
    const __half* Agr = A + (size_t)(bm * HBM + aRow) * K;

    float acc[2][8][4];
    #pragma unroll
    for (int mt = 0; mt < 2; mt++)
        #pragma unroll
        for (int nt = 0; nt < 8; nt++)
            #pragma unroll
            for (int i = 0; i < 4; i++) acc[mt][nt][i] = 0.f;

    const int NT = K / HBK;

    // ldmatrix lane addresses (within-tile), precomputed
    const int aRowL = warpM * 32 + ((lane >> 3) & 1) * 8 + (lane & 7);
    const int aColL = (lane >> 4) * 8;
    const int bRowL = ((lane >> 3) & 1) * 8 + (lane & 7);
    const int bColL = warpN * 64 + (lane >> 4) * 8;

    uint32_t aBase[2], bBase[2];
    #pragma unroll
    for (int s = 0; s < 2; s++) {
        aBase[s] = (uint32_t)__cvta_generic_to_shared(&As[s][0][0]);
        bBase[s] = (uint32_t)__cvta_generic_to_shared(&Bs[s][0][0]);
    }

    // stage tile kt into buffer s
    auto stage = [&](int s, int kt) {
        const __half* ag = Agr + kt * HBK;
        cp16(&As[s][aRow][aCh * 8],       ag + aCh * 8);
        cp16(&As[s][aRow][(aCh + 2) * 8], ag + (aCh + 2) * 8);
        #pragma unroll
        for (int i = 0; i < 2; i++) {
            const int lin = tid + i * 256;
            const int r = lin >> 4;
            const int c = lin & 15;
            cp16(&Bs[s][r][c * 8],
                 B + (size_t)(kt * HBK + r) * N + bn * HBN + c * 8);
        }
    };

    stage(0, 0); CP_COMMIT();
    if (NT > 1) { stage(1, 1); CP_COMMIT(); }

    for (int kt = 0; kt < NT; kt++) {
        if (kt + 1 < NT) { CP_WAIT1(); } else { CP_WAIT0(); }
        __syncthreads();
        const int buf = kt & 1;

        #pragma unroll
        for (int ks = 0; ks < 2; ks++) {
            uint32_t afr[2][4];
            #pragma unroll
            for (int mt = 0; mt < 2; mt++) {
                uint32_t addr = aBase[buf] +
                    (uint32_t)(((aRowL + mt * 16) * ASP + aColL + ks * 16) * 2);
                ldsm_x4(afr[mt], addr);
            }
            uint32_t bfr[8][2];
            #pragma unroll
            for (int ntp = 0; ntp < 4; ntp++) {
                uint32_t r[4];
                uint32_t addr = bBase[buf] +
                    (uint32_t)(((bRowL + ks * 16) * BSP + bColL + ntp * 16) * 2);
                ldsm_x4_t(r, addr);
                bfr[2 * ntp][0]     = r[0];
                bfr[2 * ntp][1]     = r[1];
                bfr[2 * ntp + 1][0] = r[2];
                bfr[2 * ntp + 1][1] = r[3];
            }
            #pragma unroll
            for (int mt = 0; mt < 2; mt++)
                #pragma unroll
                for (int nt = 0; nt < 8; nt++)
                    mma_f16(acc[mt][nt], afr[mt], bfr[nt]);
        }
        __syncthreads();
        if (kt + 2 < NT) { stage(buf, kt + 2); CP_COMMIT(); }
    }

    // epilogue
    #pragma unroll
    for (int mt = 0; mt < 2; mt++) {
        const int r0 = bm * HBM + warpM * 32 + mt * 16 + gp;
        #pragma unroll
        for (int nt = 0; nt < 8; nt++) {
            const int c = bn * HBN + warpN * 64 + nt * 8 + 2 * tg;
            const float b0 = bias[c];
            const float b1 = bias[c + 1];
            if (HALF_OUT) {
                __half* C = (__half*)Cv;
                __half2 v0 = __floats2half2_rn(acc[mt][nt][0] + b0, acc[mt][nt][1] + b1);
                __half2 v1 = __floats2half2_rn(acc[mt][nt][2] + b0, acc[mt][nt][3] + b1);
                *reinterpret_cast<__half2*>(&C[(size_t)r0 * N + c])       = v0;
                *reinterpret_cast<__half2*>(&C[(size_t)(r0 + 8) * N + c]) = v1;
            } else {
                float* C = (float*)Cv;
                *reinterpret_cast<float2*>(&C[(size_t)r0 * N + c]) =
                    make_float2(acc[mt][nt][0] + b0, acc[mt][nt][1] + b1);
                *reinterpret_cast<float2*>(&C[(size_t)(r0 + 8) * N + c]) =
                    make_float2(acc[mt][nt][2] + b0, acc[mt][nt][3] + b1);
            }
        }
    }
}

// ---------------------------------------------------------------------------
// fp16 tensor-core flash attention (m16n8k16, fp32 softmax), causal.
// Block: 128 threads = 4 warps; tile = 64 queries x 64 keys.
// Q frags in regs, K tile in smem (stride 72: conflict-free), V from gmem.
// P C-layout == A-layout for fp16: no shuffles needed.
// ---------------------------------------------------------------------------
#define ATQ 64
#define ATK 64
#define KSP2 72

__global__ __launch_bounds__(128)
void flash_attn_f16(const __half* __restrict__ qkv, __half* __restrict__ y)
{
    __shared__ __align__(16) __half Ks[ATK][KSP2];

    const int bh  = blockIdx.y;
    const int b   = bh >> 4;
    const int h   = bh & 15;
    const int qt  = gridDim.x - 1 - blockIdx.x;   // longest-first
    const int q0  = qt * ATQ;
    const int tid = threadIdx.x;
    const int lane = tid & 31;
    const int w    = tid >> 5;
    const int tg   = lane & 3;
    const int gp   = lane >> 2;

    const __half* base = qkv + (size_t)b * SEQ * QKVC;
    const __half* Qh = base + h * HDIM;
    const __half* Kh = base + EMBD + h * HDIM;
    const __half* Vh = base + 2 * EMBD + h * HDIM;

    const int qrow = q0 + w * 16 + gp;

    // Q fragments: 4 k-steps of 16
    uint32_t qfr[4][4];
    #pragma unroll
    for (int ks = 0; ks < 4; ks++) {
        const __half* p0 = Qh + (size_t)qrow * QKVC + ks * 16;
        const __half* p1 = Qh + (size_t)(qrow + 8) * QKVC + ks * 16;
        qfr[ks][0] = *reinterpret_cast<const uint32_t*>(p0 + 2 * tg);
        qfr[ks][1] = *reinterpret_cast<const uint32_t*>(p1 + 2 * tg);
        qfr[ks][2] = *reinterpret_cast<const uint32_t*>(p0 + 8 + 2 * tg);
        qfr[ks][3] = *reinterpret_cast<const uint32_t*>(p1 + 8 + 2 * tg);
    }

    float oacc[8][4];
    #pragma unroll
    for (int dt = 0; dt < 8; dt++)
        #pragma unroll
        for (int i = 0; i < 4; i++) oacc[dt][i] = 0.f;

    float m_lo = -1e30f, m_hi = -1e30f;
    float l_lo = 0.f,    l_hi = 0.f;

    const int ntiles = qt + 1;
    for (int kt = 0; kt < ntiles; kt++) {
        // stage K tile (64 keys x 64 halfs) with 16B copies
        #pragma unroll
        for (int i = 0; i < 4; i++) {
            const int lin = i * 128 + tid;
            const int key = lin >> 3;
            const int c8  = (lin & 7) * 8;
            *reinterpret_cast<uint4*>(&Ks[key][c8]) =
                *reinterpret_cast<const uint4*>(Kh + (size_t)(kt * ATK + key) * QKVC + c8);
        }
        __syncthreads();

        // S = Q K^T : 8 n-tiles x 4 k-steps
        float sacc[8][4];
        #pragma unroll
        for (int nt = 0; nt < 8; nt++) {
            sacc[nt][0] = sacc[nt][1] = sacc[nt][2] = sacc[nt][3] = 0.f;
            #pragma unroll
            for (int ks = 0; ks < 4; ks++) {
                uint32_t bfr[2];
                bfr[0] = *reinterpret_cast<const uint32_t*>(&Ks[nt * 8 + gp][ks * 16 + 2 * tg]);
                bfr[1] = *reinterpret_cast<const uint32_t*>(&Ks[nt * 8 + gp][ks * 16 + 8 + 2 * tg]);
                mma_f16(sacc[nt], qfr[ks], bfr);
            }
        }

        // scale + causal mask + online softmax
        const bool diag = (kt == qt);
        float tmax_lo = -1e30f, tmax_hi = -1e30f;
        #pragma unroll
        for (int nt = 0; nt < 8; nt++) {
            const int c0col = kt * ATK + nt * 8 + 2 * tg;
            float s0 = sacc[nt][0] * 0.125f;
            float s1 = sacc[nt][1] * 0.125f;
            float s2 = sacc[nt][2] * 0.125f;
            float s3 = sacc[nt][3] * 0.125f;
            if (diag) {
                if (c0col     > qrow)     s0 = -1e30f;
                if (c0col + 1 > qrow)     s1 = -1e30f;
                if (c0col     > qrow + 8) s2 = -1e30f;
                if (c0col + 1 > qrow + 8) s3 = -1e30f;
            }
            sacc[nt][0] = s0; sacc[nt][1] = s1;
            sacc[nt][2] = s2; sacc[nt][3] = s3;
            tmax_lo = fmaxf(tmax_lo, fmaxf(s0, s1));
            tmax_hi = fmaxf(tmax_hi, fmaxf(s2, s3));
        }
        tmax_lo = fmaxf(tmax_lo, __shfl_xor_sync(0xffffffffu, tmax_lo, 1));
        tmax_lo = fmaxf(tmax_lo, __shfl_xor_sync(0xffffffffu, tmax_lo, 2));
        tmax_hi = fmaxf(tmax_hi, __shfl_xor_sync(0xffffffffu, tmax_hi, 1));
        tmax_hi = fmaxf(tmax_hi, __shfl_xor_sync(0xffffffffu, tmax_hi, 2));

        const float mn_lo = fmaxf(m_lo, tmax_lo);
        const float mn_hi = fmaxf(m_hi, tmax_hi);
        const float corr_lo = __expf(m_lo - mn_lo);
        const float corr_hi = __expf(m_hi - mn_hi);
        m_lo = mn_lo; m_hi = mn_hi;

        float ps_lo = 0.f, ps_hi = 0.f;
        #pragma unroll
        for (int nt = 0; nt < 8; nt++) {
            float p0 = __expf(sacc[nt][0] - m_lo);
            float p1 = __expf(sacc[nt][1] - m_lo);
            float p2 = __expf(sacc[nt][2] - m_hi);
            float p3 = __expf(sacc[nt][3] - m_hi);
            sacc[nt][0] = p0; sacc[nt][1] = p1;
            sacc[nt][2] = p2; sacc[nt][3] = p3;
            ps_lo += p0 + p1;
            ps_hi += p2 + p3;
        }
        ps_lo += __shfl_xor_sync(0xffffffffu, ps_lo, 1);
        ps_lo += __shfl_xor_sync(0xffffffffu, ps_lo, 2);
        ps_hi += __shfl_xor_sync(0xffffffffu, ps_hi, 1);
        ps_hi += __shfl_xor_sync(0xffffffffu, ps_hi, 2);
        l_lo = l_lo * corr_lo + ps_lo;
        l_hi = l_hi * corr_hi + ps_hi;

        #pragma unroll
        for (int dt = 0; dt < 8; dt++) {
            oacc[dt][0] *= corr_lo;
            oacc[dt][1] *= corr_lo;
            oacc[dt][2] *= corr_hi;
            oacc[dt][3] *= corr_hi;
        }

        // O += P V : fp16 C-layout == A-layout, direct pack
        #pragma unroll
        for (int kk = 0; kk < 4; kk++) {
            uint32_t pa[4];
            pa[0] = h2u(__floats2half2_rn(sacc[2 * kk][0],     sacc[2 * kk][1]));
            pa[1] = h2u(__floats2half2_rn(sacc[2 * kk][2],     sacc[2 * kk][3]));
            pa[2] = h2u(__floats2half2_rn(sacc[2 * kk + 1][0], sacc[2 * kk + 1][1]));
            pa[3] = h2u(__floats2half2_rn(sacc[2 * kk + 1][2], sacc[2 * kk + 1][3]));

            const __half* v0 = Vh + (size_t)(kt * ATK + kk * 16 + 2 * tg) * QKVC;
            const __half* v1 = v0 + QKVC;
            const __half* v2 = v0 + 8 * QKVC;
            const __half* v3 = v0 + 9 * QKVC;
            #pragma unroll
            for (int dt = 0; dt < 8; dt++) {
                const int d = dt * 8 + gp;
                uint32_t bv[2];
                bv[0] = h2u(__halves2half2(v0[d], v1[d]));
                bv[1] = h2u(__halves2half2(v2[d], v3[d]));
                mma_f16(oacc[dt], pa, bv);
            }
        }
        __syncthreads();
    }

    // epilogue: normalize, write y (fp16)
    const float inv_lo = 1.f / l_lo;
    const float inv_hi = 1.f / l_hi;
    __half* y0 = y + (size_t)(b * SEQ + qrow)     * EMBD + h * HDIM;
    __half* y1 = y + (size_t)(b * SEQ + qrow + 8) * EMBD + h * HDIM;
    #pragma unroll
    for (int dt = 0; dt < 8; dt++) {
        *reinterpret_cast<__half2*>(y0 + dt * 8 + 2 * tg) =
            __floats2half2_rn(oacc[dt][0] * inv_lo, oacc[dt][1] * inv_lo);
        *reinterpret_cast<__half2*>(y1 + dt * 8 + 2 * tg) =
            __floats2half2_rn(oacc[dt][2] * inv_hi, oacc[dt][3] * inv_hi);
    }
}

// ---------------------------------------------------------------------------
// Launch: cvt x3 -> QKV GEMM -> flash attention -> proj GEMM
// ---------------------------------------------------------------------------
extern "C" void kernel_launch(void* const* d_in, const int* in_sizes, int n_in,
                              void* d_out, int out_size)
{
    const float* x      = (const float*)d_in[0];
    const float* w_attn = (const float*)d_in[1];
    const float* b_attn = (const float*)d_in[2];
    const float* w_proj = (const float*)d_in[3];
    const float* b_proj = (const float*)d_in[4];
    float* out = (float*)d_out;

    __half *xh, *wah, *wph, *qkvh, *yh;
    cudaGetSymbolAddress((void**)&xh,   g_xh);
    cudaGetSymbolAddress((void**)&wah,  g_wah);
    cudaGetSymbolAddress((void**)&wph,  g_wph);
    cudaGetSymbolAddress((void**)&qkvh, g_qkvh);
    cudaGetSymbolAddress((void**)&yh,   g_yh);

    // fp32 -> fp16 conversions
    {
        const int n4x = ROWS * EMBD / 4;
        cvt_f2h<<<(n4x + 255) / 256, 256>>>((const float4*)x, (uint2*)xh, n4x);
        const int n4a = EMBD * QKVC / 4;
        cvt_f2h<<<(n4a + 255) / 256, 256>>>((const float4*)w_attn, (uint2*)wah, n4a);
        const int n4p = EMBD * EMBD / 4;
        cvt_f2h<<<(n4p + 255) / 256, 256>>>((const float4*)w_proj, (uint2*)wph, n4p);
    }

    // QKV: [4096,1024] @ [1024,3072] + b_attn -> fp16
    gemm_f16_bias<true><<<dim3(QKVC / HBN, ROWS / HBM), 256>>>(
        xh, wah, b_attn, qkvh, ROWS, QKVC, EMBD);

    // Attention
    flash_attn_f16<<<dim3(SEQ / ATQ, BATCH * NHEAD), 128>>>(qkvh, yh);

    // Proj: [4096,1024] @ [1024,1024] + b_proj -> fp32 out
    gemm_f16_bias<false><<<dim3(EMBD / HBN, ROWS / HBM), 256>>>(
        yh, wph, b_proj, out, ROWS, EMBD, EMBD);
}